// round 14
// baseline (speedup 1.0000x reference)
#include <cuda_runtime.h>
#include <cuda_bf16.h>
#include <cstdint>

#define N_NODES 50000
#define N_EDGES 800000
#define DIM     256
#define DIM4    64
#define M_TILE  128
#define GRID_M  ((N_NODES + M_TILE - 1) / M_TILE)   // 391
#define SCAN_NB ((N_NODES + 1023) / 1024)           // 49

// ---------------- scratch (device globals: allocation-free rule) ----------
__device__ int   g_idx64;
__device__ int   g_deg_out[N_NODES];
__device__ int   g_deg_in [N_NODES];
__device__ float g_norm_s[N_NODES];
__device__ float g_norm_d[N_NODES];
__device__ int   g_row_off[N_NODES + 1];
__device__ int   g_cursor [N_NODES];
__device__ int   g_incl   [N_NODES];
__device__ int   g_bsum[64];
__device__ __align__(8) uint2 g_csr[N_EDGES];   // (src, bits(norm_s[src]))
// A operand (agg * norm_d) as bf16 hi/lo split, row-major [N_NODES, DIM]
__device__ __align__(16) unsigned short g_ahi[(size_t)N_NODES * DIM];
__device__ __align__(16) unsigned short g_alo[(size_t)N_NODES * DIM];
// W^T bf16 hi/lo splits: WT[n*DIM + k] = W[k*DIM + n]  (col-major B for mma)
__device__ __align__(16) unsigned short g_w0hi[DIM * DIM];
__device__ __align__(16) unsigned short g_w0lo[DIM * DIM];
__device__ __align__(16) unsigned short g_w1hi[DIM * DIM];
__device__ __align__(16) unsigned short g_w1lo[DIM * DIM];
__device__ float g_h1[(size_t)N_NODES * DIM];

// ---------------- fused preamble: weight split + zero + detect ---------------
__global__ void init_kernel(const int* __restrict__ src_w,
                            const float* __restrict__ W0,
                            const float* __restrict__ W1,
                            float* __restrict__ hg) {
    int blk = blockIdx.x;
    int tid = threadIdx.x;
    int i = blk * 256 + tid;
    if (i < N_NODES) { g_deg_out[i] = 0; g_deg_in[i] = 0; }
    if (i < 2 * DIM) hg[i] = 0.f;

    {
        const float* W = (blk < DIM) ? W0 : W1;
        unsigned short* hiT = (blk < DIM) ? g_w0hi : g_w1hi;
        unsigned short* loT = (blk < DIM) ? g_w0lo : g_w1lo;
        int k = blk & (DIM - 1), n = tid;
        float x = W[k * DIM + n];
        __nv_bfloat16 h = __float2bfloat16_rn(x);
        float r = x - __bfloat162float(h);
        __nv_bfloat16 l = __float2bfloat16_rn(r);
        hiT[n * DIM + k] = __bfloat16_as_ushort(h);
        loT[n * DIM + k] = __bfloat16_as_ushort(l);
    }

    if (blk == 511) {
        __shared__ int any;
        if (tid == 0) any = 0;
        __syncthreads();
        for (int k = tid; k < 4096; k += 256)
            if (src_w[2 * k + 1] != 0) any = 1;   // benign race (same value)
        __syncthreads();
        if (tid == 0) g_idx64 = (any == 0) ? 1 : 0;
    }
}
__device__ __forceinline__ int load_idx(const void* p, int i, int is64) {
    return is64 ? (int)((const long long*)p)[i] : ((const int*)p)[i];
}

// ---------------- degrees ---------------------------------------------------
__global__ void degree_kernel(const void* __restrict__ src,
                              const void* __restrict__ dst) {
    int e = blockIdx.x * blockDim.x + threadIdx.x;
    if (e >= N_EDGES) return;
    int is64 = g_idx64;
    atomicAdd(&g_deg_out[load_idx(src, e, is64)], 1);
    atomicAdd(&g_deg_in [load_idx(dst, e, is64)], 1);
}

// ---------------- scan block phase + fused norm computation ------------------
__global__ void scan_blocks_kernel() {
    __shared__ int sh[1024];
    int i = blockIdx.x * 1024 + threadIdx.x;
    int v = (i < N_NODES) ? g_deg_in[i] : 0;
    if (i < N_NODES) {
        g_norm_s[i] = rsqrtf(fmaxf((float)g_deg_out[i], 1.f));
        g_norm_d[i] = rsqrtf(fmaxf((float)v, 1.f));
    }
    sh[threadIdx.x] = v;
    __syncthreads();
    for (int off = 1; off < 1024; off <<= 1) {
        int t = (threadIdx.x >= off) ? sh[threadIdx.x - off] : 0;
        __syncthreads();
        sh[threadIdx.x] += t;
        __syncthreads();
    }
    if (i < N_NODES) g_incl[i] = sh[threadIdx.x];
    if (threadIdx.x == 1023) g_bsum[blockIdx.x] = sh[1023];
}

// finalize with inlined bsum-prefix (each CTA re-scans the 49 block sums)
__global__ void scan_finalize_kernel() {
    __shared__ int sh[SCAN_NB];
    if (threadIdx.x < SCAN_NB) sh[threadIdx.x] = g_bsum[threadIdx.x];
    __syncthreads();
    int i = blockIdx.x * blockDim.x + threadIdx.x;
    if (i >= N_NODES) return;
    int blk = i >> 10;
    int off = 0;
    for (int b = 0; b < blk; b++) off += sh[b];
    int o = off + g_incl[i] - g_deg_in[i];
    g_row_off[i] = o;
    g_cursor[i]  = o;
    if (i == 0) g_row_off[N_NODES] = N_EDGES;
}

// fill CSR: slot gets packed (src, norm_s[src])
__global__ void fill_kernel(const void* __restrict__ src,
                            const void* __restrict__ dst) {
    int e = blockIdx.x * blockDim.x + threadIdx.x;
    if (e >= N_EDGES) return;
    int is64 = g_idx64;
    int s = load_idx(src, e, is64);
    int d = load_idx(dst, e, is64);
    int pos = atomicAdd(&g_cursor[d], 1);
    g_csr[pos] = make_uint2((uint32_t)s, __float_as_uint(g_norm_s[s]));
}

// ---------------- aggregation: 1 warp/node, unroll-2, fused split -----------
__device__ __forceinline__ void fma4(float4& a, float w, const float4& v) {
    a.x += w * v.x; a.y += w * v.y; a.z += w * v.z; a.w += w * v.w;
}
__device__ __forceinline__ void split_store(float4 acc, size_t off) {
    unsigned short hs[4], ls[4];
    float vals[4] = {acc.x, acc.y, acc.z, acc.w};
#pragma unroll
    for (int i = 0; i < 4; i++) {
        __nv_bfloat16 hb = __float2bfloat16_rn(vals[i]);
        float r = vals[i] - __bfloat162float(hb);
        __nv_bfloat16 lb = __float2bfloat16_rn(r);
        hs[i] = __bfloat16_as_ushort(hb);
        ls[i] = __bfloat16_as_ushort(lb);
    }
    *(uint2*)&g_ahi[off] = make_uint2(((uint32_t)hs[1] << 16) | hs[0],
                                      ((uint32_t)hs[3] << 16) | hs[2]);
    *(uint2*)&g_alo[off] = make_uint2(((uint32_t)ls[1] << 16) | ls[0],
                                      ((uint32_t)ls[3] << 16) | ls[2]);
}

__global__ __launch_bounds__(256)
void gather_kernel(const float4* __restrict__ h) {
    int d    = (int)((blockIdx.x * blockDim.x + threadIdx.x) >> 5);
    int lane = threadIdx.x & 31;
    if (d >= N_NODES) return;
    int beg = g_row_off[d];
    int end = g_row_off[d + 1];
    float4 acc0 = make_float4(0.f, 0.f, 0.f, 0.f);
    float4 acc1 = make_float4(0.f, 0.f, 0.f, 0.f);
    int j = beg;
    for (; j + 1 < end; j += 2) {
        uint2 e0 = g_csr[j], e1 = g_csr[j + 1];
        const float4* r0 = h + (size_t)e0.x * DIM4;
        const float4* r1 = h + (size_t)e1.x * DIM4;
        float w0 = __uint_as_float(e0.y);
        float w1 = __uint_as_float(e1.y);
        float4 a0 = r0[lane];
        float4 a1 = r1[lane];
        float4 b0 = r0[lane + 32];
        float4 b1 = r1[lane + 32];
        fma4(acc0, w0, a0); fma4(acc0, w1, a1);
        fma4(acc1, w0, b0); fma4(acc1, w1, b1);
    }
    if (j < end) {
        uint2 e0 = g_csr[j];
        float w0 = __uint_as_float(e0.y);
        const float4* r0 = h + (size_t)e0.x * DIM4;
        fma4(acc0, w0, r0[lane]);
        fma4(acc1, w0, r0[lane + 32]);
    }
    float nd = g_norm_d[d];
    acc0.x *= nd; acc0.y *= nd; acc0.z *= nd; acc0.w *= nd;
    acc1.x *= nd; acc1.y *= nd; acc1.z *= nd; acc1.w *= nd;
    split_store(acc0, (size_t)d * DIM + lane * 4);
    split_store(acc1, (size_t)d * DIM + (lane + 32) * 4);
}

// ---------------- mma.sync GEMM: out = prelu(A @ W + b) ---------------------
#define PITCH   24
#define SA_SZ   (128 * PITCH * 2)            // 6144 B per buffer
#define SB_SZ   (256 * PITCH * 2)            // 12288 B per buffer
#define SM_AHI(b) ((b) * SA_SZ)
#define SM_ALO(b) (2 * SA_SZ + (b) * SA_SZ)
#define SM_BHI(b) (4 * SA_SZ + (b) * SB_SZ)
#define SM_BLO(b) (4 * SA_SZ + 2 * SB_SZ + (b) * SB_SZ)
#define SM_TOTAL  (4 * SA_SZ + 4 * SB_SZ)    // 73728 B

__device__ __forceinline__ void mma16816(float* c, const uint32_t* a,
                                         uint32_t b0, uint32_t b1) {
    asm volatile(
        "mma.sync.aligned.m16n8k16.row.col.f32.bf16.bf16.f32 "
        "{%0,%1,%2,%3}, {%4,%5,%6,%7}, {%8,%9}, {%0,%1,%2,%3};"
        : "+f"(c[0]), "+f"(c[1]), "+f"(c[2]), "+f"(c[3])
        : "r"(a[0]), "r"(a[1]), "r"(a[2]), "r"(a[3]), "r"(b0), "r"(b1));
}

__global__ __launch_bounds__(256, 1)
void gemm_mma_kernel(const unsigned short* __restrict__ Ahi,
                     const unsigned short* __restrict__ Alo,
                     const unsigned short* __restrict__ Bhi,
                     const unsigned short* __restrict__ Blo,
                     const float* __restrict__ bias,
                     const float* __restrict__ prelu_a,
                     float* __restrict__ out, int M) {
    extern __shared__ char smem[];
    const int tid  = threadIdx.x;
    const int wid  = tid >> 5;
    const int lane = tid & 31;
    const int bm   = blockIdx.x * M_TILE;
    const int wm   = (wid >> 1) * 32;
    const int wn   = (wid & 1) * 128;
    const int qrow = lane >> 2;
    const int qcol = lane & 3;

    const int a_row  = tid >> 1;
    const int a_half = tid & 1;
    const int a_gr   = bm + a_row;

    float c[2][16][4];
#pragma unroll
    for (int mt = 0; mt < 2; mt++)
#pragma unroll
        for (int nt = 0; nt < 16; nt++)
#pragma unroll
            for (int i = 0; i < 4; i++) c[mt][nt][i] = 0.f;

    uint4 pAh, pAl, pB0h, pB1h, pB0l, pB1l;

    {
        pAh = make_uint4(0, 0, 0, 0); pAl = pAh;
        if (a_gr < M) {
            pAh = *(const uint4*)(Ahi + (size_t)a_gr * DIM + a_half * 8);
            pAl = *(const uint4*)(Alo + (size_t)a_gr * DIM + a_half * 8);
        }
        const uint4* pbh = (const uint4*)(Bhi + (size_t)tid * DIM);
        const uint4* pbl = (const uint4*)(Blo + (size_t)tid * DIM);
        pB0h = pbh[0]; pB1h = pbh[1];
        pB0l = pbl[0]; pB1l = pbl[1];
    }
    *(uint4*)(smem + SM_AHI(0) + a_row * 48 + a_half * 16) = pAh;
    *(uint4*)(smem + SM_ALO(0) + a_row * 48 + a_half * 16) = pAl;
    *(uint4*)(smem + SM_BHI(0) + tid * 48)      = pB0h;
    *(uint4*)(smem + SM_BHI(0) + tid * 48 + 16) = pB1h;
    *(uint4*)(smem + SM_BLO(0) + tid * 48)      = pB0l;
    *(uint4*)(smem + SM_BLO(0) + tid * 48 + 16) = pB1l;
    __syncthreads();

    for (int ks = 0; ks < 16; ks++) {
        const int buf = ks & 1;
        if (ks < 15) {
            int k0 = (ks + 1) * 16;
            pAh = make_uint4(0, 0, 0, 0); pAl = pAh;
            if (a_gr < M) {
                pAh = *(const uint4*)(Ahi + (size_t)a_gr * DIM + k0 + a_half * 8);
                pAl = *(const uint4*)(Alo + (size_t)a_gr * DIM + k0 + a_half * 8);
            }
            const uint4* pbh = (const uint4*)(Bhi + (size_t)tid * DIM + k0);
            const uint4* pbl = (const uint4*)(Blo + (size_t)tid * DIM + k0);
            pB0h = pbh[0]; pB1h = pbh[1];
            pB0l = pbl[0]; pB1l = pbl[1];
        }
        uint32_t ah[2][4], al[2][4];
#pragma unroll
        for (int mt = 0; mt < 2; mt++) {
            int base = (wm + mt * 16 + qrow) * 48 + qcol * 4;
            ah[mt][0] = *(const uint32_t*)(smem + SM_AHI(buf) + base);
            ah[mt][1] = *(const uint32_t*)(smem + SM_AHI(buf) + base + 8 * 48);
            ah[mt][2] = *(const uint32_t*)(smem + SM_AHI(buf) + base + 16);
            ah[mt][3] = *(const uint32_t*)(smem + SM_AHI(buf) + base + 8 * 48 + 16);
            al[mt][0] = *(const uint32_t*)(smem + SM_ALO(buf) + base);
            al[mt][1] = *(const uint32_t*)(smem + SM_ALO(buf) + base + 8 * 48);
            al[mt][2] = *(const uint32_t*)(smem + SM_ALO(buf) + base + 16);
            al[mt][3] = *(const uint32_t*)(smem + SM_ALO(buf) + base + 8 * 48 + 16);
        }
#pragma unroll
        for (int nt = 0; nt < 16; nt++) {
            int bb = (wn + nt * 8 + qrow) * 48 + qcol * 4;
            uint32_t bh0 = *(const uint32_t*)(smem + SM_BHI(buf) + bb);
            uint32_t bh1 = *(const uint32_t*)(smem + SM_BHI(buf) + bb + 16);
            uint32_t bl0 = *(const uint32_t*)(smem + SM_BLO(buf) + bb);
            uint32_t bl1 = *(const uint32_t*)(smem + SM_BLO(buf) + bb + 16);
#pragma unroll
            for (int mt = 0; mt < 2; mt++) {
                mma16816(c[mt][nt], ah[mt], bh0, bh1);
                mma16816(c[mt][nt], ah[mt], bl0, bl1);
                mma16816(c[mt][nt], al[mt], bh0, bh1);
            }
        }
        if (ks < 15) {
            int nb = buf ^ 1;
            *(uint4*)(smem + SM_AHI(nb) + a_row * 48 + a_half * 16) = pAh;
            *(uint4*)(smem + SM_ALO(nb) + a_row * 48 + a_half * 16) = pAl;
            *(uint4*)(smem + SM_BHI(nb) + tid * 48)      = pB0h;
            *(uint4*)(smem + SM_BHI(nb) + tid * 48 + 16) = pB1h;
            *(uint4*)(smem + SM_BLO(nb) + tid * 48)      = pB0l;
            *(uint4*)(smem + SM_BLO(nb) + tid * 48 + 16) = pB1l;
        }
        __syncthreads();
    }

    const float pa = __ldg(prelu_a);
#pragma unroll
    for (int nt = 0; nt < 16; nt++) {
        int col = wn + nt * 8 + qcol * 2;
        float bx = bias[col], by = bias[col + 1];
#pragma unroll
        for (int mt = 0; mt < 2; mt++) {
            int r0 = bm + wm + mt * 16 + qrow;
            float v0 = c[mt][nt][0] + bx;
            float v1 = c[mt][nt][1] + by;
            float v2 = c[mt][nt][2] + bx;
            float v3 = c[mt][nt][3] + by;
            v0 = (v0 >= 0.f) ? v0 : pa * v0;
            v1 = (v1 >= 0.f) ? v1 : pa * v1;
            v2 = (v2 >= 0.f) ? v2 : pa * v2;
            v3 = (v3 >= 0.f) ? v3 : pa * v3;
            if (r0 < M)
                *(float2*)(out + (size_t)r0 * DIM + col) = make_float2(v0, v1);
            if (r0 + 8 < M)
                *(float2*)(out + (size_t)(r0 + 8) * DIM + col) = make_float2(v2, v3);
        }
    }
}

// ---------------- readout: 500 blocks x 100 rows ----------------------------
__global__ void colsum_kernel(const float* __restrict__ h,
                              float* __restrict__ hg) {
    int c = threadIdx.x;
    int r0 = blockIdx.x * 100;
    float s = 0.f;
    for (int r = 0; r < 100; r++)
        s += h[(size_t)(r0 + r) * DIM + c];
    atomicAdd(&hg[c], s);
}

// ---------------- launch ----------------------------------------------------
extern "C" void kernel_launch(void* const* d_in, const int* in_sizes, int n_in,
                              void* d_out, int out_size) {
    const float* feat = (const float*)d_in[0];
    const void*  src  = d_in[1];
    const void*  dst  = d_in[2];
    const float* W0   = (const float*)d_in[3];
    const float* b0   = (const float*)d_in[4];
    const float* W1   = (const float*)d_in[5];
    const float* b1   = (const float*)d_in[6];
    const float* pa   = (const float*)d_in[7];
    float* out = (float*)d_out;
    float* hg  = out + (size_t)N_NODES * DIM;

    void *p_ahi, *p_alo, *p_w0hi, *p_w0lo, *p_w1hi, *p_w1lo, *p_h1;
    cudaGetSymbolAddress(&p_ahi,  g_ahi);
    cudaGetSymbolAddress(&p_alo,  g_alo);
    cudaGetSymbolAddress(&p_w0hi, g_w0hi);
    cudaGetSymbolAddress(&p_w0lo, g_w0lo);
    cudaGetSymbolAddress(&p_w1hi, g_w1hi);
    cudaGetSymbolAddress(&p_w1lo, g_w1lo);
    cudaGetSymbolAddress(&p_h1,   g_h1);

    cudaFuncSetAttribute(gemm_mma_kernel,
                         cudaFuncAttributeMaxDynamicSharedMemorySize, SM_TOTAL);

    const int TB = 256;
    const int nodeBlk = (N_NODES + TB - 1) / TB;
    const int edgeBlk = (N_EDGES + TB - 1) / TB;
    const int gatherBlk = (N_NODES * 32 + TB - 1) / TB;   // 1 warp/node

    // ---- preprocessing (5 launches) ----
    init_kernel<<<2 * DIM, TB>>>((const int*)src, W0, W1, hg);
    degree_kernel<<<edgeBlk, TB>>>(src, dst);
    scan_blocks_kernel<<<SCAN_NB, 1024>>>();              // also computes norms
    scan_finalize_kernel<<<nodeBlk, TB>>>();              // bsum scan inlined
    fill_kernel<<<edgeBlk, TB>>>(src, dst);

    // ---- layer 1 ----
    gather_kernel<<<gatherBlk, TB>>>((const float4*)feat);
    gemm_mma_kernel<<<GRID_M, TB, SM_TOTAL>>>(
        (const unsigned short*)p_ahi, (const unsigned short*)p_alo,
        (const unsigned short*)p_w0hi, (const unsigned short*)p_w0lo,
        b0, pa, (float*)p_h1, N_NODES);
    colsum_kernel<<<500, TB>>>((const float*)p_h1, hg);

    // ---- layer 2 ----
    gather_kernel<<<gatherBlk, TB>>>((const float4*)p_h1);
    gemm_mma_kernel<<<GRID_M, TB, SM_TOTAL>>>(
        (const unsigned short*)p_ahi, (const unsigned short*)p_alo,
        (const unsigned short*)p_w1hi, (const unsigned short*)p_w1lo,
        b1, pa, out, N_NODES);
    colsum_kernel<<<500, TB>>>(out, hg + DIM);
}

// round 15
// speedup vs baseline: 1.4124x; 1.4124x over previous
#include <cuda_runtime.h>
#include <cuda_bf16.h>
#include <cstdint>

#define N_NODES 50000
#define N_EDGES 800000
#define DIM     256
#define DIM4    64
#define M_TILE  128
#define GRID_M  ((N_NODES + M_TILE - 1) / M_TILE)   // 391
#define SCAN_NB ((N_NODES + 1023) / 1024)           // 49

// ---------------- scratch (device globals: allocation-free rule) ----------
__device__ int   g_idx64;
__device__ int   g_deg_out[N_NODES];
__device__ int   g_deg_in [N_NODES];
__device__ float g_norm_s[N_NODES];
__device__ float g_norm_d[N_NODES];
__device__ int   g_row_off[N_NODES + 1];
__device__ int   g_cursor [N_NODES];
__device__ int   g_incl   [N_NODES];
__device__ int   g_bsum[64];
__device__ int   g_csr_src[N_EDGES];
__device__ float g_csr_w  [N_EDGES];     // norm_s[src] per CSR slot
// A operand (agg * norm_d) as bf16 hi/lo split, row-major [N_NODES, DIM]
__device__ __align__(16) unsigned short g_ahi[(size_t)N_NODES * DIM];
__device__ __align__(16) unsigned short g_alo[(size_t)N_NODES * DIM];
// W^T bf16 hi/lo splits: WT[n*DIM + k] = W[k*DIM + n]  (col-major B for mma)
__device__ __align__(16) unsigned short g_w0hi[DIM * DIM];
__device__ __align__(16) unsigned short g_w0lo[DIM * DIM];
__device__ __align__(16) unsigned short g_w1hi[DIM * DIM];
__device__ __align__(16) unsigned short g_w1lo[DIM * DIM];
__device__ float g_h1[(size_t)N_NODES * DIM];

// ---------------- fused preamble: weight split + zero + detect ---------------
__global__ void init_kernel(const int* __restrict__ src_w,
                            const float* __restrict__ W0,
                            const float* __restrict__ W1,
                            float* __restrict__ hg) {
    int blk = blockIdx.x;
    int tid = threadIdx.x;
    int i = blk * 256 + tid;
    if (i < N_NODES) { g_deg_out[i] = 0; g_deg_in[i] = 0; }
    if (i < 2 * DIM) hg[i] = 0.f;

    {
        const float* W = (blk < DIM) ? W0 : W1;
        unsigned short* hiT = (blk < DIM) ? g_w0hi : g_w1hi;
        unsigned short* loT = (blk < DIM) ? g_w0lo : g_w1lo;
        int k = blk & (DIM - 1), n = tid;
        float x = W[k * DIM + n];
        __nv_bfloat16 h = __float2bfloat16_rn(x);
        float r = x - __bfloat162float(h);
        __nv_bfloat16 l = __float2bfloat16_rn(r);
        hiT[n * DIM + k] = __bfloat16_as_ushort(h);
        loT[n * DIM + k] = __bfloat16_as_ushort(l);
    }

    if (blk == 511) {
        __shared__ int any;
        if (tid == 0) any = 0;
        __syncthreads();
        for (int k = tid; k < 4096; k += 256)
            if (src_w[2 * k + 1] != 0) any = 1;   // benign race (same value)
        __syncthreads();
        if (tid == 0) g_idx64 = (any == 0) ? 1 : 0;
    }
}
__device__ __forceinline__ int load_idx(const void* p, int i, int is64) {
    return is64 ? (int)((const long long*)p)[i] : ((const int*)p)[i];
}

// ---------------- degrees ---------------------------------------------------
__global__ void degree_kernel(const void* __restrict__ src,
                              const void* __restrict__ dst) {
    int e = blockIdx.x * blockDim.x + threadIdx.x;
    if (e >= N_EDGES) return;
    int is64 = g_idx64;
    atomicAdd(&g_deg_out[load_idx(src, e, is64)], 1);
    atomicAdd(&g_deg_in [load_idx(dst, e, is64)], 1);
}

// ---------------- scan block phase + fused norm computation ------------------
__global__ void scan_blocks_kernel() {
    __shared__ int sh[1024];
    int i = blockIdx.x * 1024 + threadIdx.x;
    int v = (i < N_NODES) ? g_deg_in[i] : 0;
    if (i < N_NODES) {
        g_norm_s[i] = rsqrtf(fmaxf((float)g_deg_out[i], 1.f));
        g_norm_d[i] = rsqrtf(fmaxf((float)v, 1.f));
    }
    sh[threadIdx.x] = v;
    __syncthreads();
    for (int off = 1; off < 1024; off <<= 1) {
        int t = (threadIdx.x >= off) ? sh[threadIdx.x - off] : 0;
        __syncthreads();
        sh[threadIdx.x] += t;
        __syncthreads();
    }
    if (i < N_NODES) g_incl[i] = sh[threadIdx.x];
    if (threadIdx.x == 1023) g_bsum[blockIdx.x] = sh[1023];
}

// finalize with inlined bsum-prefix (each CTA re-scans the 49 block sums)
__global__ void scan_finalize_kernel() {
    __shared__ int sh[SCAN_NB];
    if (threadIdx.x < SCAN_NB) sh[threadIdx.x] = g_bsum[threadIdx.x];
    __syncthreads();
    int i = blockIdx.x * blockDim.x + threadIdx.x;
    if (i >= N_NODES) return;
    int blk = i >> 10;
    int off = 0;
    for (int b = 0; b < blk; b++) off += sh[b];
    int o = off + g_incl[i] - g_deg_in[i];
    g_row_off[i] = o;
    g_cursor[i]  = o;
    if (i == 0) g_row_off[N_NODES] = N_EDGES;
}

// fill CSR: slot gets (src, norm_s[src])
__global__ void fill_kernel(const void* __restrict__ src,
                            const void* __restrict__ dst) {
    int e = blockIdx.x * blockDim.x + threadIdx.x;
    if (e >= N_EDGES) return;
    int is64 = g_idx64;
    int s = load_idx(src, e, is64);
    int d = load_idx(dst, e, is64);
    int pos = atomicAdd(&g_cursor[d], 1);
    g_csr_src[pos] = s;
    g_csr_w[pos]   = g_norm_s[s];
}

// ---------------- aggregation: 1 warp/node, unroll-2, fused split -----------
__device__ __forceinline__ void fma4(float4& a, float w, const float4& v) {
    a.x += w * v.x; a.y += w * v.y; a.z += w * v.z; a.w += w * v.w;
}
__device__ __forceinline__ void split_store(float4 acc, size_t off) {
    unsigned short hs[4], ls[4];
    float vals[4] = {acc.x, acc.y, acc.z, acc.w};
#pragma unroll
    for (int i = 0; i < 4; i++) {
        __nv_bfloat16 hb = __float2bfloat16_rn(vals[i]);
        float r = vals[i] - __bfloat162float(hb);
        __nv_bfloat16 lb = __float2bfloat16_rn(r);
        hs[i] = __bfloat16_as_ushort(hb);
        ls[i] = __bfloat16_as_ushort(lb);
    }
    *(uint2*)&g_ahi[off] = make_uint2(((uint32_t)hs[1] << 16) | hs[0],
                                      ((uint32_t)hs[3] << 16) | hs[2]);
    *(uint2*)&g_alo[off] = make_uint2(((uint32_t)ls[1] << 16) | ls[0],
                                      ((uint32_t)ls[3] << 16) | ls[2]);
}

__global__ __launch_bounds__(256)
void gather_kernel(const float4* __restrict__ h) {
    int d    = (int)((blockIdx.x * blockDim.x + threadIdx.x) >> 5);
    int lane = threadIdx.x & 31;
    if (d >= N_NODES) return;
    int beg = g_row_off[d];
    int end = g_row_off[d + 1];
    float4 acc0 = make_float4(0.f, 0.f, 0.f, 0.f);
    float4 acc1 = make_float4(0.f, 0.f, 0.f, 0.f);
    int j = beg;
    for (; j + 1 < end; j += 2) {
        int   s0 = g_csr_src[j],   s1 = g_csr_src[j + 1];
        float w0 = g_csr_w[j],     w1 = g_csr_w[j + 1];
        const float4* r0 = h + (size_t)s0 * DIM4;
        const float4* r1 = h + (size_t)s1 * DIM4;
        float4 a0 = r0[lane];
        float4 a1 = r1[lane];
        float4 b0 = r0[lane + 32];
        float4 b1 = r1[lane + 32];
        fma4(acc0, w0, a0); fma4(acc0, w1, a1);
        fma4(acc1, w0, b0); fma4(acc1, w1, b1);
    }
    if (j < end) {
        int   s0 = g_csr_src[j];
        float w0 = g_csr_w[j];
        const float4* r0 = h + (size_t)s0 * DIM4;
        fma4(acc0, w0, r0[lane]);
        fma4(acc1, w0, r0[lane + 32]);
    }
    float nd = g_norm_d[d];
    acc0.x *= nd; acc0.y *= nd; acc0.z *= nd; acc0.w *= nd;
    acc1.x *= nd; acc1.y *= nd; acc1.z *= nd; acc1.w *= nd;
    split_store(acc0, (size_t)d * DIM + lane * 4);
    split_store(acc1, (size_t)d * DIM + (lane + 32) * 4);
}

// ---------------- mma.sync GEMM: out = prelu(A @ W + b) ---------------------
#define PITCH   24
#define SA_SZ   (128 * PITCH * 2)            // 6144 B per buffer
#define SB_SZ   (256 * PITCH * 2)            // 12288 B per buffer
#define SM_AHI(b) ((b) * SA_SZ)
#define SM_ALO(b) (2 * SA_SZ + (b) * SA_SZ)
#define SM_BHI(b) (4 * SA_SZ + (b) * SB_SZ)
#define SM_BLO(b) (4 * SA_SZ + 2 * SB_SZ + (b) * SB_SZ)
#define SM_TOTAL  (4 * SA_SZ + 4 * SB_SZ)    // 73728 B

__device__ __forceinline__ void mma16816(float* c, const uint32_t* a,
                                         uint32_t b0, uint32_t b1) {
    asm volatile(
        "mma.sync.aligned.m16n8k16.row.col.f32.bf16.bf16.f32 "
        "{%0,%1,%2,%3}, {%4,%5,%6,%7}, {%8,%9}, {%0,%1,%2,%3};"
        : "+f"(c[0]), "+f"(c[1]), "+f"(c[2]), "+f"(c[3])
        : "r"(a[0]), "r"(a[1]), "r"(a[2]), "r"(a[3]), "r"(b0), "r"(b1));
}

__global__ __launch_bounds__(256, 1)
void gemm_mma_kernel(const unsigned short* __restrict__ Ahi,
                     const unsigned short* __restrict__ Alo,
                     const unsigned short* __restrict__ Bhi,
                     const unsigned short* __restrict__ Blo,
                     const float* __restrict__ bias,
                     const float* __restrict__ prelu_a,
                     float* __restrict__ out, int M) {
    extern __shared__ char smem[];
    const int tid  = threadIdx.x;
    const int wid  = tid >> 5;
    const int lane = tid & 31;
    const int bm   = blockIdx.x * M_TILE;
    const int wm   = (wid >> 1) * 32;
    const int wn   = (wid & 1) * 128;
    const int qrow = lane >> 2;
    const int qcol = lane & 3;

    const int a_row  = tid >> 1;
    const int a_half = tid & 1;
    const int a_gr   = bm + a_row;

    float c[2][16][4];
#pragma unroll
    for (int mt = 0; mt < 2; mt++)
#pragma unroll
        for (int nt = 0; nt < 16; nt++)
#pragma unroll
            for (int i = 0; i < 4; i++) c[mt][nt][i] = 0.f;

    uint4 pAh, pAl, pB0h, pB1h, pB0l, pB1l;

    {
        pAh = make_uint4(0, 0, 0, 0); pAl = pAh;
        if (a_gr < M) {
            pAh = *(const uint4*)(Ahi + (size_t)a_gr * DIM + a_half * 8);
            pAl = *(const uint4*)(Alo + (size_t)a_gr * DIM + a_half * 8);
        }
        const uint4* pbh = (const uint4*)(Bhi + (size_t)tid * DIM);
        const uint4* pbl = (const uint4*)(Blo + (size_t)tid * DIM);
        pB0h = pbh[0]; pB1h = pbh[1];
        pB0l = pbl[0]; pB1l = pbl[1];
    }
    *(uint4*)(smem + SM_AHI(0) + a_row * 48 + a_half * 16) = pAh;
    *(uint4*)(smem + SM_ALO(0) + a_row * 48 + a_half * 16) = pAl;
    *(uint4*)(smem + SM_BHI(0) + tid * 48)      = pB0h;
    *(uint4*)(smem + SM_BHI(0) + tid * 48 + 16) = pB1h;
    *(uint4*)(smem + SM_BLO(0) + tid * 48)      = pB0l;
    *(uint4*)(smem + SM_BLO(0) + tid * 48 + 16) = pB1l;
    __syncthreads();

    for (int ks = 0; ks < 16; ks++) {
        const int buf = ks & 1;
        if (ks < 15) {
            int k0 = (ks + 1) * 16;
            pAh = make_uint4(0, 0, 0, 0); pAl = pAh;
            if (a_gr < M) {
                pAh = *(const uint4*)(Ahi + (size_t)a_gr * DIM + k0 + a_half * 8);
                pAl = *(const uint4*)(Alo + (size_t)a_gr * DIM + k0 + a_half * 8);
            }
            const uint4* pbh = (const uint4*)(Bhi + (size_t)tid * DIM + k0);
            const uint4* pbl = (const uint4*)(Blo + (size_t)tid * DIM + k0);
            pB0h = pbh[0]; pB1h = pbh[1];
            pB0l = pbl[0]; pB1l = pbl[1];
        }
        uint32_t ah[2][4], al[2][4];
#pragma unroll
        for (int mt = 0; mt < 2; mt++) {
            int base = (wm + mt * 16 + qrow) * 48 + qcol * 4;
            ah[mt][0] = *(const uint32_t*)(smem + SM_AHI(buf) + base);
            ah[mt][1] = *(const uint32_t*)(smem + SM_AHI(buf) + base + 8 * 48);
            ah[mt][2] = *(const uint32_t*)(smem + SM_AHI(buf) + base + 16);
            ah[mt][3] = *(const uint32_t*)(smem + SM_AHI(buf) + base + 8 * 48 + 16);
            al[mt][0] = *(const uint32_t*)(smem + SM_ALO(buf) + base);
            al[mt][1] = *(const uint32_t*)(smem + SM_ALO(buf) + base + 8 * 48);
            al[mt][2] = *(const uint32_t*)(smem + SM_ALO(buf) + base + 16);
            al[mt][3] = *(const uint32_t*)(smem + SM_ALO(buf) + base + 8 * 48 + 16);
        }
#pragma unroll
        for (int nt = 0; nt < 16; nt++) {
            int bb = (wn + nt * 8 + qrow) * 48 + qcol * 4;
            uint32_t bh0 = *(const uint32_t*)(smem + SM_BHI(buf) + bb);
            uint32_t bh1 = *(const uint32_t*)(smem + SM_BHI(buf) + bb + 16);
            uint32_t bl0 = *(const uint32_t*)(smem + SM_BLO(buf) + bb);
            uint32_t bl1 = *(const uint32_t*)(smem + SM_BLO(buf) + bb + 16);
#pragma unroll
            for (int mt = 0; mt < 2; mt++) {
                mma16816(c[mt][nt], ah[mt], bh0, bh1);
                mma16816(c[mt][nt], ah[mt], bl0, bl1);
                mma16816(c[mt][nt], al[mt], bh0, bh1);
            }
        }
        if (ks < 15) {
            int nb = buf ^ 1;
            *(uint4*)(smem + SM_AHI(nb) + a_row * 48 + a_half * 16) = pAh;
            *(uint4*)(smem + SM_ALO(nb) + a_row * 48 + a_half * 16) = pAl;
            *(uint4*)(smem + SM_BHI(nb) + tid * 48)      = pB0h;
            *(uint4*)(smem + SM_BHI(nb) + tid * 48 + 16) = pB1h;
            *(uint4*)(smem + SM_BLO(nb) + tid * 48)      = pB0l;
            *(uint4*)(smem + SM_BLO(nb) + tid * 48 + 16) = pB1l;
        }
        __syncthreads();
    }

    const float pa = __ldg(prelu_a);
#pragma unroll
    for (int nt = 0; nt < 16; nt++) {
        int col = wn + nt * 8 + qcol * 2;
        float bx = bias[col], by = bias[col + 1];
#pragma unroll
        for (int mt = 0; mt < 2; mt++) {
            int r0 = bm + wm + mt * 16 + qrow;
            float v0 = c[mt][nt][0] + bx;
            float v1 = c[mt][nt][1] + by;
            float v2 = c[mt][nt][2] + bx;
            float v3 = c[mt][nt][3] + by;
            v0 = (v0 >= 0.f) ? v0 : pa * v0;
            v1 = (v1 >= 0.f) ? v1 : pa * v1;
            v2 = (v2 >= 0.f) ? v2 : pa * v2;
            v3 = (v3 >= 0.f) ? v3 : pa * v3;
            if (r0 < M)
                *(float2*)(out + (size_t)r0 * DIM + col) = make_float2(v0, v1);
            if (r0 + 8 < M)
                *(float2*)(out + (size_t)(r0 + 8) * DIM + col) = make_float2(v2, v3);
        }
    }
}

// ---------------- readout: 500 blocks x 100 rows ----------------------------
__global__ void colsum_kernel(const float* __restrict__ h,
                              float* __restrict__ hg) {
    int c = threadIdx.x;
    int r0 = blockIdx.x * 100;
    float s = 0.f;
    for (int r = 0; r < 100; r++)
        s += h[(size_t)(r0 + r) * DIM + c];
    atomicAdd(&hg[c], s);
}

// ---------------- launch ----------------------------------------------------
extern "C" void kernel_launch(void* const* d_in, const int* in_sizes, int n_in,
                              void* d_out, int out_size) {
    const float* feat = (const float*)d_in[0];
    const void*  src  = d_in[1];
    const void*  dst  = d_in[2];
    const float* W0   = (const float*)d_in[3];
    const float* b0   = (const float*)d_in[4];
    const float* W1   = (const float*)d_in[5];
    const float* b1   = (const float*)d_in[6];
    const float* pa   = (const float*)d_in[7];
    float* out = (float*)d_out;
    float* hg  = out + (size_t)N_NODES * DIM;

    void *p_ahi, *p_alo, *p_w0hi, *p_w0lo, *p_w1hi, *p_w1lo, *p_h1;
    cudaGetSymbolAddress(&p_ahi,  g_ahi);
    cudaGetSymbolAddress(&p_alo,  g_alo);
    cudaGetSymbolAddress(&p_w0hi, g_w0hi);
    cudaGetSymbolAddress(&p_w0lo, g_w0lo);
    cudaGetSymbolAddress(&p_w1hi, g_w1hi);
    cudaGetSymbolAddress(&p_w1lo, g_w1lo);
    cudaGetSymbolAddress(&p_h1,   g_h1);

    cudaFuncSetAttribute(gemm_mma_kernel,
                         cudaFuncAttributeMaxDynamicSharedMemorySize, SM_TOTAL);

    const int TB = 256;
    const int nodeBlk = (N_NODES + TB - 1) / TB;
    const int edgeBlk = (N_EDGES + TB - 1) / TB;
    const int gatherBlk = (N_NODES * 32 + TB - 1) / TB;   // 1 warp/node

    // ---- preprocessing (5 launches) ----
    init_kernel<<<2 * DIM, TB>>>((const int*)src, W0, W1, hg);
    degree_kernel<<<edgeBlk, TB>>>(src, dst);
    scan_blocks_kernel<<<SCAN_NB, 1024>>>();              // also computes norms
    scan_finalize_kernel<<<nodeBlk, TB>>>();              // bsum scan inlined
    fill_kernel<<<edgeBlk, TB>>>(src, dst);

    // ---- layer 1 ----
    gather_kernel<<<gatherBlk, TB>>>((const float4*)feat);
    gemm_mma_kernel<<<GRID_M, TB, SM_TOTAL>>>(
        (const unsigned short*)p_ahi, (const unsigned short*)p_alo,
        (const unsigned short*)p_w0hi, (const unsigned short*)p_w0lo,
        b0, pa, (float*)p_h1, N_NODES);
    colsum_kernel<<<500, TB>>>((const float*)p_h1, hg);

    // ---- layer 2 ----
    gather_kernel<<<gatherBlk, TB>>>((const float4*)p_h1);
    gemm_mma_kernel<<<GRID_M, TB, SM_TOTAL>>>(
        (const unsigned short*)p_ahi, (const unsigned short*)p_alo,
        (const unsigned short*)p_w1hi, (const unsigned short*)p_w1lo,
        b1, pa, out, N_NODES);
    colsum_kernel<<<500, TB>>>(out, hg + DIM);
}

// round 16
// speedup vs baseline: 1.4232x; 1.0077x over previous
#include <cuda_runtime.h>
#include <cuda_bf16.h>
#include <cstdint>

#define N_NODES 50000
#define N_EDGES 800000
#define DIM     256
#define DIM4    64
#define M_TILE  128
#define GRID_M  ((N_NODES + M_TILE - 1) / M_TILE)   // 391
#define SCAN_NB ((N_NODES + 1023) / 1024)           // 49

// ---------------- scratch (device globals: allocation-free rule) ----------
__device__ int   g_idx64;
__device__ int   g_deg_out[N_NODES];
__device__ int   g_deg_in [N_NODES];
__device__ float g_norm_s[N_NODES];
__device__ float g_norm_d[N_NODES];
__device__ int   g_row_off[N_NODES + 1];
__device__ int   g_cursor [N_NODES];
__device__ int   g_incl   [N_NODES];
__device__ int   g_bsum[64];
__device__ int   g_csr_src[N_EDGES];
__device__ float g_csr_w  [N_EDGES];     // norm_s[src] per CSR slot
// A operand (agg * norm_d) as bf16 hi/lo split, row-major [N_NODES, DIM]
__device__ __align__(16) unsigned short g_ahi[(size_t)N_NODES * DIM];
__device__ __align__(16) unsigned short g_alo[(size_t)N_NODES * DIM];
// W^T bf16 hi/lo splits: WT[n*DIM + k] = W[k*DIM + n]  (col-major B for mma)
__device__ __align__(16) unsigned short g_w0hi[DIM * DIM];
__device__ __align__(16) unsigned short g_w0lo[DIM * DIM];
__device__ __align__(16) unsigned short g_w1hi[DIM * DIM];
__device__ __align__(16) unsigned short g_w1lo[DIM * DIM];
__device__ float g_h1[(size_t)N_NODES * DIM];

// ---------------- zero + dtype detect (critical-path preamble) --------------
__global__ void zero_detect_kernel(const int* __restrict__ src_w,
                                   float* __restrict__ hg) {
    int i = blockIdx.x * blockDim.x + threadIdx.x;
    if (i < N_NODES) { g_deg_out[i] = 0; g_deg_in[i] = 0; }
    if (i < 2 * DIM) hg[i] = 0.f;
    if (blockIdx.x == 0) {
        __shared__ int any;
        if (threadIdx.x == 0) any = 0;
        __syncthreads();
        for (int k = threadIdx.x; k < 4096; k += 256)
            if (src_w[2 * k + 1] != 0) any = 1;   // benign race (same value)
        __syncthreads();
        if (threadIdx.x == 0) g_idx64 = (any == 0) ? 1 : 0;
    }
}
__device__ __forceinline__ int load_idx(const void* p, int i, int is64) {
    return is64 ? (int)((const long long*)p)[i] : ((const int*)p)[i];
}

// ---------------- weight split (side stream; independent until GEMM1) -------
__global__ void split_w_kernel(const float* __restrict__ W0,
                               const float* __restrict__ W1) {
    int blk = blockIdx.x;
    const float* W = (blk < DIM) ? W0 : W1;
    unsigned short* hiT = (blk < DIM) ? g_w0hi : g_w1hi;
    unsigned short* loT = (blk < DIM) ? g_w0lo : g_w1lo;
    int k = blk & (DIM - 1), n = threadIdx.x;
    float x = W[k * DIM + n];
    __nv_bfloat16 h = __float2bfloat16_rn(x);
    float r = x - __bfloat162float(h);
    __nv_bfloat16 l = __float2bfloat16_rn(r);
    hiT[n * DIM + k] = __bfloat16_as_ushort(h);
    loT[n * DIM + k] = __bfloat16_as_ushort(l);
}

// ---------------- degrees ---------------------------------------------------
__global__ void degree_kernel(const void* __restrict__ src,
                              const void* __restrict__ dst) {
    int e = blockIdx.x * blockDim.x + threadIdx.x;
    if (e >= N_EDGES) return;
    int is64 = g_idx64;
    atomicAdd(&g_deg_out[load_idx(src, e, is64)], 1);
    atomicAdd(&g_deg_in [load_idx(dst, e, is64)], 1);
}

// ---------------- scan block phase + fused norm computation ------------------
__global__ void scan_blocks_kernel() {
    __shared__ int sh[1024];
    int i = blockIdx.x * 1024 + threadIdx.x;
    int v = (i < N_NODES) ? g_deg_in[i] : 0;
    if (i < N_NODES) {
        g_norm_s[i] = rsqrtf(fmaxf((float)g_deg_out[i], 1.f));
        g_norm_d[i] = rsqrtf(fmaxf((float)v, 1.f));
    }
    sh[threadIdx.x] = v;
    __syncthreads();
    for (int off = 1; off < 1024; off <<= 1) {
        int t = (threadIdx.x >= off) ? sh[threadIdx.x - off] : 0;
        __syncthreads();
        sh[threadIdx.x] += t;
        __syncthreads();
    }
    if (i < N_NODES) g_incl[i] = sh[threadIdx.x];
    if (threadIdx.x == 1023) g_bsum[blockIdx.x] = sh[1023];
}

// finalize with inlined bsum-prefix (each CTA re-scans the 49 block sums)
__global__ void scan_finalize_kernel() {
    __shared__ int sh[SCAN_NB];
    if (threadIdx.x < SCAN_NB) sh[threadIdx.x] = g_bsum[threadIdx.x];
    __syncthreads();
    int i = blockIdx.x * blockDim.x + threadIdx.x;
    if (i >= N_NODES) return;
    int blk = i >> 10;
    int off = 0;
    for (int b = 0; b < blk; b++) off += sh[b];
    int o = off + g_incl[i] - g_deg_in[i];
    g_row_off[i] = o;
    g_cursor[i]  = o;
    if (i == 0) g_row_off[N_NODES] = N_EDGES;
}

// fill CSR: slot gets (src, norm_s[src])
__global__ void fill_kernel(const void* __restrict__ src,
                            const void* __restrict__ dst) {
    int e = blockIdx.x * blockDim.x + threadIdx.x;
    if (e >= N_EDGES) return;
    int is64 = g_idx64;
    int s = load_idx(src, e, is64);
    int d = load_idx(dst, e, is64);
    int pos = atomicAdd(&g_cursor[d], 1);
    g_csr_src[pos] = s;
    g_csr_w[pos]   = g_norm_s[s];
}

// ---------------- aggregation: 1 warp/node, unroll-2, fused split -----------
__device__ __forceinline__ void fma4(float4& a, float w, const float4& v) {
    a.x += w * v.x; a.y += w * v.y; a.z += w * v.z; a.w += w * v.w;
}
__device__ __forceinline__ void split_store(float4 acc, size_t off) {
    unsigned short hs[4], ls[4];
    float vals[4] = {acc.x, acc.y, acc.z, acc.w};
#pragma unroll
    for (int i = 0; i < 4; i++) {
        __nv_bfloat16 hb = __float2bfloat16_rn(vals[i]);
        float r = vals[i] - __bfloat162float(hb);
        __nv_bfloat16 lb = __float2bfloat16_rn(r);
        hs[i] = __bfloat16_as_ushort(hb);
        ls[i] = __bfloat16_as_ushort(lb);
    }
    *(uint2*)&g_ahi[off] = make_uint2(((uint32_t)hs[1] << 16) | hs[0],
                                      ((uint32_t)hs[3] << 16) | hs[2]);
    *(uint2*)&g_alo[off] = make_uint2(((uint32_t)ls[1] << 16) | ls[0],
                                      ((uint32_t)ls[3] << 16) | ls[2]);
}

__global__ __launch_bounds__(256)
void gather_kernel(const float4* __restrict__ h) {
    int d    = (int)((blockIdx.x * blockDim.x + threadIdx.x) >> 5);
    int lane = threadIdx.x & 31;
    if (d >= N_NODES) return;
    int beg = g_row_off[d];
    int end = g_row_off[d + 1];
    float4 acc0 = make_float4(0.f, 0.f, 0.f, 0.f);
    float4 acc1 = make_float4(0.f, 0.f, 0.f, 0.f);
    int j = beg;
    for (; j + 1 < end; j += 2) {
        int   s0 = g_csr_src[j],   s1 = g_csr_src[j + 1];
        float w0 = g_csr_w[j],     w1 = g_csr_w[j + 1];
        const float4* r0 = h + (size_t)s0 * DIM4;
        const float4* r1 = h + (size_t)s1 * DIM4;
        float4 a0 = r0[lane];
        float4 a1 = r1[lane];
        float4 b0 = r0[lane + 32];
        float4 b1 = r1[lane + 32];
        fma4(acc0, w0, a0); fma4(acc0, w1, a1);
        fma4(acc1, w0, b0); fma4(acc1, w1, b1);
    }
    if (j < end) {
        int   s0 = g_csr_src[j];
        float w0 = g_csr_w[j];
        const float4* r0 = h + (size_t)s0 * DIM4;
        fma4(acc0, w0, r0[lane]);
        fma4(acc1, w0, r0[lane + 32]);
    }
    float nd = g_norm_d[d];
    acc0.x *= nd; acc0.y *= nd; acc0.z *= nd; acc0.w *= nd;
    acc1.x *= nd; acc1.y *= nd; acc1.z *= nd; acc1.w *= nd;
    split_store(acc0, (size_t)d * DIM + lane * 4);
    split_store(acc1, (size_t)d * DIM + (lane + 32) * 4);
}

// ---------------- mma.sync GEMM: out = prelu(A @ W + b) ---------------------
#define PITCH   24
#define SA_SZ   (128 * PITCH * 2)            // 6144 B per buffer
#define SB_SZ   (256 * PITCH * 2)            // 12288 B per buffer
#define SM_AHI(b) ((b) * SA_SZ)
#define SM_ALO(b) (2 * SA_SZ + (b) * SA_SZ)
#define SM_BHI(b) (4 * SA_SZ + (b) * SB_SZ)
#define SM_BLO(b) (4 * SA_SZ + 2 * SB_SZ + (b) * SB_SZ)
#define SM_TOTAL  (4 * SA_SZ + 4 * SB_SZ)    // 73728 B

__device__ __forceinline__ void mma16816(float* c, const uint32_t* a,
                                         uint32_t b0, uint32_t b1) {
    asm volatile(
        "mma.sync.aligned.m16n8k16.row.col.f32.bf16.bf16.f32 "
        "{%0,%1,%2,%3}, {%4,%5,%6,%7}, {%8,%9}, {%0,%1,%2,%3};"
        : "+f"(c[0]), "+f"(c[1]), "+f"(c[2]), "+f"(c[3])
        : "r"(a[0]), "r"(a[1]), "r"(a[2]), "r"(a[3]), "r"(b0), "r"(b1));
}

__global__ __launch_bounds__(256, 1)
void gemm_mma_kernel(const unsigned short* __restrict__ Ahi,
                     const unsigned short* __restrict__ Alo,
                     const unsigned short* __restrict__ Bhi,
                     const unsigned short* __restrict__ Blo,
                     const float* __restrict__ bias,
                     const float* __restrict__ prelu_a,
                     float* __restrict__ out, int M) {
    extern __shared__ char smem[];
    const int tid  = threadIdx.x;
    const int wid  = tid >> 5;
    const int lane = tid & 31;
    const int bm   = blockIdx.x * M_TILE;
    const int wm   = (wid >> 1) * 32;
    const int wn   = (wid & 1) * 128;
    const int qrow = lane >> 2;
    const int qcol = lane & 3;

    const int a_row  = tid >> 1;
    const int a_half = tid & 1;
    const int a_gr   = bm + a_row;

    float c[2][16][4];
#pragma unroll
    for (int mt = 0; mt < 2; mt++)
#pragma unroll
        for (int nt = 0; nt < 16; nt++)
#pragma unroll
            for (int i = 0; i < 4; i++) c[mt][nt][i] = 0.f;

    uint4 pAh, pAl, pB0h, pB1h, pB0l, pB1l;

    {
        pAh = make_uint4(0, 0, 0, 0); pAl = pAh;
        if (a_gr < M) {
            pAh = *(const uint4*)(Ahi + (size_t)a_gr * DIM + a_half * 8);
            pAl = *(const uint4*)(Alo + (size_t)a_gr * DIM + a_half * 8);
        }
        const uint4* pbh = (const uint4*)(Bhi + (size_t)tid * DIM);
        const uint4* pbl = (const uint4*)(Blo + (size_t)tid * DIM);
        pB0h = pbh[0]; pB1h = pbh[1];
        pB0l = pbl[0]; pB1l = pbl[1];
    }
    *(uint4*)(smem + SM_AHI(0) + a_row * 48 + a_half * 16) = pAh;
    *(uint4*)(smem + SM_ALO(0) + a_row * 48 + a_half * 16) = pAl;
    *(uint4*)(smem + SM_BHI(0) + tid * 48)      = pB0h;
    *(uint4*)(smem + SM_BHI(0) + tid * 48 + 16) = pB1h;
    *(uint4*)(smem + SM_BLO(0) + tid * 48)      = pB0l;
    *(uint4*)(smem + SM_BLO(0) + tid * 48 + 16) = pB1l;
    __syncthreads();

    for (int ks = 0; ks < 16; ks++) {
        const int buf = ks & 1;
        if (ks < 15) {
            int k0 = (ks + 1) * 16;
            pAh = make_uint4(0, 0, 0, 0); pAl = pAh;
            if (a_gr < M) {
                pAh = *(const uint4*)(Ahi + (size_t)a_gr * DIM + k0 + a_half * 8);
                pAl = *(const uint4*)(Alo + (size_t)a_gr * DIM + k0 + a_half * 8);
            }
            const uint4* pbh = (const uint4*)(Bhi + (size_t)tid * DIM + k0);
            const uint4* pbl = (const uint4*)(Blo + (size_t)tid * DIM + k0);
            pB0h = pbh[0]; pB1h = pbh[1];
            pB0l = pbl[0]; pB1l = pbl[1];
        }
        uint32_t ah[2][4], al[2][4];
#pragma unroll
        for (int mt = 0; mt < 2; mt++) {
            int base = (wm + mt * 16 + qrow) * 48 + qcol * 4;
            ah[mt][0] = *(const uint32_t*)(smem + SM_AHI(buf) + base);
            ah[mt][1] = *(const uint32_t*)(smem + SM_AHI(buf) + base + 8 * 48);
            ah[mt][2] = *(const uint32_t*)(smem + SM_AHI(buf) + base + 16);
            ah[mt][3] = *(const uint32_t*)(smem + SM_AHI(buf) + base + 8 * 48 + 16);
            al[mt][0] = *(const uint32_t*)(smem + SM_ALO(buf) + base);
            al[mt][1] = *(const uint32_t*)(smem + SM_ALO(buf) + base + 8 * 48);
            al[mt][2] = *(const uint32_t*)(smem + SM_ALO(buf) + base + 16);
            al[mt][3] = *(const uint32_t*)(smem + SM_ALO(buf) + base + 8 * 48 + 16);
        }
#pragma unroll
        for (int nt = 0; nt < 16; nt++) {
            int bb = (wn + nt * 8 + qrow) * 48 + qcol * 4;
            uint32_t bh0 = *(const uint32_t*)(smem + SM_BHI(buf) + bb);
            uint32_t bh1 = *(const uint32_t*)(smem + SM_BHI(buf) + bb + 16);
            uint32_t bl0 = *(const uint32_t*)(smem + SM_BLO(buf) + bb);
            uint32_t bl1 = *(const uint32_t*)(smem + SM_BLO(buf) + bb + 16);
#pragma unroll
            for (int mt = 0; mt < 2; mt++) {
                mma16816(c[mt][nt], ah[mt], bh0, bh1);
                mma16816(c[mt][nt], ah[mt], bl0, bl1);
                mma16816(c[mt][nt], al[mt], bh0, bh1);
            }
        }
        if (ks < 15) {
            int nb = buf ^ 1;
            *(uint4*)(smem + SM_AHI(nb) + a_row * 48 + a_half * 16) = pAh;
            *(uint4*)(smem + SM_ALO(nb) + a_row * 48 + a_half * 16) = pAl;
            *(uint4*)(smem + SM_BHI(nb) + tid * 48)      = pB0h;
            *(uint4*)(smem + SM_BHI(nb) + tid * 48 + 16) = pB1h;
            *(uint4*)(smem + SM_BLO(nb) + tid * 48)      = pB0l;
            *(uint4*)(smem + SM_BLO(nb) + tid * 48 + 16) = pB1l;
        }
        __syncthreads();
    }

    const float pa = __ldg(prelu_a);
#pragma unroll
    for (int nt = 0; nt < 16; nt++) {
        int col = wn + nt * 8 + qcol * 2;
        float bx = bias[col], by = bias[col + 1];
#pragma unroll
        for (int mt = 0; mt < 2; mt++) {
            int r0 = bm + wm + mt * 16 + qrow;
            float v0 = c[mt][nt][0] + bx;
            float v1 = c[mt][nt][1] + by;
            float v2 = c[mt][nt][2] + bx;
            float v3 = c[mt][nt][3] + by;
            v0 = (v0 >= 0.f) ? v0 : pa * v0;
            v1 = (v1 >= 0.f) ? v1 : pa * v1;
            v2 = (v2 >= 0.f) ? v2 : pa * v2;
            v3 = (v3 >= 0.f) ? v3 : pa * v3;
            if (r0 < M)
                *(float2*)(out + (size_t)r0 * DIM + col) = make_float2(v0, v1);
            if (r0 + 8 < M)
                *(float2*)(out + (size_t)(r0 + 8) * DIM + col) = make_float2(v2, v3);
        }
    }
}

// ---------------- readout: 500 blocks x 100 rows ----------------------------
__global__ void colsum_kernel(const float* __restrict__ h,
                              float* __restrict__ hg) {
    int c = threadIdx.x;
    int r0 = blockIdx.x * 100;
    float s = 0.f;
    for (int r = 0; r < 100; r++)
        s += h[(size_t)(r0 + r) * DIM + c];
    atomicAdd(&hg[c], s);
}

// ---------------- launch ----------------------------------------------------
extern "C" void kernel_launch(void* const* d_in, const int* in_sizes, int n_in,
                              void* d_out, int out_size) {
    const float* feat = (const float*)d_in[0];
    const void*  src  = d_in[1];
    const void*  dst  = d_in[2];
    const float* W0   = (const float*)d_in[3];
    const float* b0   = (const float*)d_in[4];
    const float* W1   = (const float*)d_in[5];
    const float* b1   = (const float*)d_in[6];
    const float* pa   = (const float*)d_in[7];
    float* out = (float*)d_out;
    float* hg  = out + (size_t)N_NODES * DIM;

    void *p_ahi, *p_alo, *p_w0hi, *p_w0lo, *p_w1hi, *p_w1lo, *p_h1;
    cudaGetSymbolAddress(&p_ahi,  g_ahi);
    cudaGetSymbolAddress(&p_alo,  g_alo);
    cudaGetSymbolAddress(&p_w0hi, g_w0hi);
    cudaGetSymbolAddress(&p_w0lo, g_w0lo);
    cudaGetSymbolAddress(&p_w1hi, g_w1hi);
    cudaGetSymbolAddress(&p_w1lo, g_w1lo);
    cudaGetSymbolAddress(&p_h1,   g_h1);

    cudaFuncSetAttribute(gemm_mma_kernel,
                         cudaFuncAttributeMaxDynamicSharedMemorySize, SM_TOTAL);

    const int TB = 256;
    const int nodeBlk = (N_NODES + TB - 1) / TB;
    const int edgeBlk = (N_EDGES + TB - 1) / TB;
    const int gatherBlk = (N_NODES * 32 + TB - 1) / TB;   // 1 warp/node

    // Side stream forked into the capture graph via events.
    cudaStream_t s1;
    cudaStreamCreateWithFlags(&s1, cudaStreamNonBlocking);
    cudaEvent_t e_fork, e_w, e_cs1;
    cudaEventCreateWithFlags(&e_fork, cudaEventDisableTiming);
    cudaEventCreateWithFlags(&e_w,    cudaEventDisableTiming);
    cudaEventCreateWithFlags(&e_cs1,  cudaEventDisableTiming);

    // ---- fork: weight split runs beside the degree/scan/fill chain ----
    cudaEventRecord(e_fork, 0);
    cudaStreamWaitEvent(s1, e_fork, 0);
    split_w_kernel<<<2 * DIM, TB, 0, s1>>>(W0, W1);
    cudaEventRecord(e_w, s1);

    // ---- critical path: preprocessing ----
    zero_detect_kernel<<<nodeBlk, TB>>>((const int*)src, hg);
    degree_kernel<<<edgeBlk, TB>>>(src, dst);
    scan_blocks_kernel<<<SCAN_NB, 1024>>>();              // also computes norms
    scan_finalize_kernel<<<nodeBlk, TB>>>();              // bsum scan inlined
    fill_kernel<<<edgeBlk, TB>>>(src, dst);

    // ---- layer 1 ----
    gather_kernel<<<gatherBlk, TB>>>((const float4*)feat);
    cudaStreamWaitEvent(0, e_w, 0);                       // weights ready
    gemm_mma_kernel<<<GRID_M, TB, SM_TOTAL>>>(
        (const unsigned short*)p_ahi, (const unsigned short*)p_alo,
        (const unsigned short*)p_w0hi, (const unsigned short*)p_w0lo,
        b0, pa, (float*)p_h1, N_NODES);

    // ---- colsum1 forked beside gather2 (both only READ g_h1) ----
    cudaEventRecord(e_fork, 0);
    cudaStreamWaitEvent(s1, e_fork, 0);
    colsum_kernel<<<500, TB, 0, s1>>>((const float*)p_h1, hg);
    cudaEventRecord(e_cs1, s1);

    // ---- layer 2 ----
    gather_kernel<<<gatherBlk, TB>>>((const float4*)p_h1);
    gemm_mma_kernel<<<GRID_M, TB, SM_TOTAL>>>(
        (const unsigned short*)p_ahi, (const unsigned short*)p_alo,
        (const unsigned short*)p_w1hi, (const unsigned short*)p_w1lo,
        b1, pa, out, N_NODES);
    colsum_kernel<<<500, TB>>>(out, hg + DIM);

    // ---- join side stream back into the graph ----
    cudaStreamWaitEvent(0, e_cs1, 0);

    cudaEventDestroy(e_fork);
    cudaEventDestroy(e_w);
    cudaEventDestroy(e_cs1);
    cudaStreamDestroy(s1);
}